// round 11
// baseline (speedup 1.0000x reference)
#include <cuda_runtime.h>
#include <cuda_fp16.h>
#include <cstdint>

// Problem constants
#define B_  8
#define T_  1024
#define C_  768
#define H_  12
#define HS_ 64
#define M_TOT (B_*T_)        // 8192
#define N_TOT (3*C_)         // 2304
#define K_TOT C_             // 768

// ---------------------------------------------------------------------------
// Device-global scratch (fp16 single plane)
// ---------------------------------------------------------------------------
__device__ __align__(16) __half g_Q16[B_*H_*T_*HS_];
__device__ __align__(16) __half g_K16[B_*H_*T_*HS_];
__device__ __align__(16) __half g_V16[B_*H_*T_*HS_];

__device__ __align__(16) __half g_x16[M_TOT*K_TOT];
__device__ __align__(16) __half g_w16[N_TOT*K_TOT];

// ---------------------------------------------------------------------------
// PTX helpers (base ISA only)
// ---------------------------------------------------------------------------
__device__ __forceinline__ uint32_t smem_u32(const void* p) {
    uint32_t a;
    asm("{ .reg .u64 t; cvta.to.shared.u64 t, %1; cvt.u32.u64 %0, t; }"
        : "=r"(a) : "l"(p));
    return a;
}
__device__ __forceinline__ void cp_async16(uint32_t s, const void* g) {
    asm volatile("cp.async.cg.shared.global [%0], [%1], 16;" :: "r"(s), "l"(g));
}
__device__ __forceinline__ void cp_commit() {
    asm volatile("cp.async.commit_group;" ::: "memory");
}
__device__ __forceinline__ void cp_wait2() {
    asm volatile("cp.async.wait_group 2;" ::: "memory");
}
__device__ __forceinline__ void cp_wait1() {
    asm volatile("cp.async.wait_group 1;" ::: "memory");
}
__device__ __forceinline__ void cp_wait0() {
    asm volatile("cp.async.wait_group 0;" ::: "memory");
}
__device__ __forceinline__ void ldmatrix_x4(uint32_t& r0, uint32_t& r1,
                                            uint32_t& r2, uint32_t& r3,
                                            uint32_t addr) {
    asm volatile("ldmatrix.sync.aligned.m8n8.x4.shared.b16 {%0,%1,%2,%3}, [%4];"
                 : "=r"(r0), "=r"(r1), "=r"(r2), "=r"(r3) : "r"(addr));
}
__device__ __forceinline__ void ldmatrix_x4_trans(uint32_t& r0, uint32_t& r1,
                                                  uint32_t& r2, uint32_t& r3,
                                                  uint32_t addr) {
    asm volatile("ldmatrix.sync.aligned.m8n8.x4.trans.shared.b16 {%0,%1,%2,%3}, [%4];"
                 : "=r"(r0), "=r"(r1), "=r"(r2), "=r"(r3) : "r"(addr));
}
__device__ __forceinline__ void mma_f16(float& c0, float& c1, float& c2, float& c3,
                                        uint32_t a0, uint32_t a1, uint32_t a2, uint32_t a3,
                                        uint32_t b0, uint32_t b1) {
    asm volatile(
        "mma.sync.aligned.m16n8k16.row.col.f32.f16.f16.f32 "
        "{%0,%1,%2,%3}, {%4,%5,%6,%7}, {%8,%9}, {%0,%1,%2,%3};"
        : "+f"(c0), "+f"(c1), "+f"(c2), "+f"(c3)
        : "r"(a0), "r"(a1), "r"(a2), "r"(a3), "r"(b0), "r"(b1));
}
__device__ __forceinline__ uint32_t pk_h2(__half lo, __half hi) {
    __half2 v = __halves2half2(lo, hi);
    return *reinterpret_cast<uint32_t*>(&v);
}
#define SWZ128(o) ((o) ^ (((o) >> 3) & 0x70))

// ---------------------------------------------------------------------------
// Kernel 0: fp32 -> fp16 single plane for x and W
// ---------------------------------------------------------------------------
__global__ __launch_bounds__(256) void split_kernel(const float* __restrict__ x,
                                                    const float* __restrict__ W)
{
    const int nqx = (M_TOT * K_TOT) / 4;
    const int nqw = (N_TOT * K_TOT) / 4;
    for (int q = blockIdx.x * blockDim.x + threadIdx.x; q < nqx + nqw;
         q += gridDim.x * blockDim.x) {
        const float4* src; __half* dst; int qq;
        if (q < nqx) { src = (const float4*)x; dst = g_x16; qq = q; }
        else         { src = (const float4*)W; dst = g_w16; qq = q - nqx; }
        const float4 v = src[qq];
        __half2* p = (__half2*)(dst + (size_t)qq * 4);
        p[0] = __halves2half2(__float2half_rn(v.x), __float2half_rn(v.y));
        p[1] = __halves2half2(__float2half_rn(v.z), __float2half_rn(v.w));
    }
}

// ---------------------------------------------------------------------------
// Kernel 1: HMMA QKV GEMM — fp16 single pass, 3-stage cp.async pipeline.
// ---------------------------------------------------------------------------
#define ROWB 80
#define TILE_B (128*ROWB)
#define BUF_B  (2*TILE_B)        // 20480 B per stage
#define GEMM_SMEM (3*BUF_B)      // 61440 B
#define NITER  24

__global__ __launch_bounds__(256) void qkv_hmma_kernel(const float* __restrict__ bias)
{
    extern __shared__ char smg[];
    const uint32_t sbase = smem_u32(smg);

    const int tid  = threadIdx.x;
    const int warp = tid >> 5;
    const int lane = tid & 31;
    const int m0 = blockIdx.y * 128;
    const int n0 = blockIdx.x * 128;
    const int wm0 = (warp >> 2) * 64;
    const int wn0 = (warp & 3) * 32;

    auto fill = [&](int it, int buf) {
        const int kc = it * 32;
        const uint32_t base = sbase + buf * BUF_B;
        #pragma unroll
        for (int j = 0; j < 4; j++) {
            const int seg = tid + j * 256;
            const int arr = seg >> 9;
            const int w = seg & 511;
            const int r = w >> 2, c = w & 3;
            const __half* src = (arr == 0) ? g_x16 : g_w16;
            const int row = ((arr == 0) ? m0 : n0) + r;
            cp_async16(base + arr * TILE_B + r * ROWB + c * 16,
                       src + (size_t)row * K_TOT + kc + c * 8);
        }
        cp_commit();
    };

    float acc[4][4][4] = {};

    fill(0, 0);
    fill(1, 1);

    for (int i = 0; i < NITER; i++) {
        const int buf = i % 3;
        if (i + 2 < NITER) fill(i + 2, (i + 2) % 3);
        if (i + 2 < NITER)      cp_wait2();
        else if (i + 1 < NITER) cp_wait1();
        else                    cp_wait0();
        __syncthreads();

        const uint32_t sA = sbase + buf * BUF_B;
        const uint32_t sB = sA + TILE_B;

        uint32_t bf[4][4];
        #pragma unroll
        for (int nt = 0; nt < 4; nt++) {
            const int off = (wn0 + nt * 8 + (lane & 7)) * ROWB + (lane >> 3) * 16;
            ldmatrix_x4(bf[nt][0], bf[nt][1], bf[nt][2], bf[nt][3], sB + off);
        }

        #pragma unroll
        for (int ks = 0; ks < 2; ks++) {
            #pragma unroll
            for (int mt = 0; mt < 4; mt++) {
                const int off = (wm0 + mt * 16 + (lane & 15)) * ROWB
                              + ks * 32 + (lane >> 4) * 16;
                uint32_t a0, a1, a2, a3;
                ldmatrix_x4(a0, a1, a2, a3, sA + off);
                #pragma unroll
                for (int nt = 0; nt < 4; nt++) {
                    float* c = acc[mt][nt];
                    mma_f16(c[0], c[1], c[2], c[3], a0, a1, a2, a3,
                            bf[nt][ks * 2 + 0], bf[nt][ks * 2 + 1]);
                }
            }
        }
        __syncthreads();
    }

    // Epilogue: bias add; Q/K/V -> fp16 single plane, scatter [B,H,T,hs]
    const int g  = lane >> 2;
    const int tq = lane & 3;
    #pragma unroll
    for (int nt = 0; nt < 4; nt++) {
        const int n = n0 + wn0 + nt * 8 + tq * 2;
        const float b0 = __ldg(bias + n);
        const float b1 = __ldg(bias + n + 1);
        const int three = n / C_;
        const int rem   = n - three * C_;
        const int head  = rem >> 6;
        const int d     = rem & 63;
        __half* dst = (three == 0) ? g_Q16 : (three == 1) ? g_K16 : g_V16;
        #pragma unroll
        for (int mt = 0; mt < 4; mt++) {
            #pragma unroll
            for (int half = 0; half < 2; half++) {
                const int m = m0 + wm0 + mt * 16 + g + half * 8;
                const int bb = m >> 10;
                const int t  = m & 1023;
                const float f0 = acc[mt][nt][half * 2 + 0] + b0;
                const float f1 = acc[mt][nt][half * 2 + 1] + b1;
                const size_t idx = ((size_t)(bb * H_ + head) * T_ + t) * HS_ + d;
                *reinterpret_cast<__half2*>(dst + idx) =
                    __halves2half2(__float2half_rn(f0), __float2half_rn(f1));
            }
        }
    }
}

// ---------------------------------------------------------------------------
// Kernel 2: fused causal ReLU attention — R9 shape (64-q CTAs, 4 warps),
// with Q A-fragments hoisted out of the kt loop.
// smem: Q16 (8KB) + 2 x (K16|V16) buffers (2 x 16KB) = 40KB.
// ---------------------------------------------------------------------------
#define AT_BUF0  8192
#define AT_BUF_B 16384
#define AT_SMEM  40960

__global__ __launch_bounds__(128) void attn_hmma_kernel(float* __restrict__ out)
{
    extern __shared__ char smema[];
    const uint32_t sb = smem_u32(smema);
    const int tid  = threadIdx.x;
    const int warp = tid >> 5;
    const int lane = tid & 31;
    const int bh = blockIdx.x;
    const int qt = (int)gridDim.y - 1 - (int)blockIdx.y;  // heavy tiles first
    const int b  = bh / H_;
    const int h  = bh - b * H_;
    const size_t hbase = (size_t)bh * T_ * HS_;

    // ---- load Q tile (single plane), swizzled 128B rows
    {
        #pragma unroll
        for (int j = 0; j < 4; j++) {
            const int w = tid + j * 128;            // 0..511
            const int r = w >> 3, c = w & 7;
            cp_async16(sb + SWZ128(r * 128 + c * 16),
                       g_Q16 + hbase + (size_t)(qt * 64 + r) * HS_ + c * 8);
        }
    }
    auto fillkv = [&](int kt, int buf) {
        #pragma unroll
        for (int j = 0; j < 8; j++) {
            const int seg = tid + j * 128;          // 0..1023
            const int arr = seg >> 9;               // 0:K16 1:V16
            const int w = seg & 511;
            const int r = w >> 3, c = w & 7;
            const __half* src = arr ? g_V16 : g_K16;
            cp_async16(sb + AT_BUF0 + buf * AT_BUF_B + arr * 8192
                           + SWZ128(r * 128 + c * 16),
                       src + hbase + (size_t)(kt * 64 + r) * HS_ + c * 8);
        }
        cp_commit();
    };

    fillkv(0, 0);   // Q loads ride in this group

    float y[8][4] = {};
    const float scale = 0.125f;
    const int rlo = warp * 16 + (lane >> 2);
    const int cbase = 2 * (lane & 3);

    uint32_t af[4][4];   // Q fragments, loop-invariant; loaded at kt==0

    for (int kt = 0; kt <= qt; kt++) {
        const int buf = kt & 1;
        if (kt < qt) { fillkv(kt + 1, buf ^ 1); cp_wait1(); }
        else         { cp_wait0(); }
        __syncthreads();

        const uint32_t sQ = sb;
        const uint32_t sK = sb + AT_BUF0 + buf * AT_BUF_B;
        const uint32_t sV = sK + 8192;

        if (kt == 0) {
            #pragma unroll
            for (int ks = 0; ks < 4; ks++) {
                const int row = warp * 16 + (lane & 15);
                const int colb = ks * 32 + (lane >> 4) * 16;
                ldmatrix_x4(af[ks][0], af[ks][1], af[ks][2], af[ks][3],
                            sQ + SWZ128(row * 128 + colb));
            }
        }

        // ---- S = Q16 · K16^T (single pass)
        float S[8][4] = {};
        #pragma unroll
        for (int kp = 0; kp < 2; kp++) {
            uint32_t bs[8][4];
            #pragma unroll
            for (int nt = 0; nt < 8; nt++) {
                const int row = nt * 8 + (lane & 7);
                const int colb = kp * 64 + (lane >> 3) * 16;
                ldmatrix_x4(bs[nt][0], bs[nt][1], bs[nt][2], bs[nt][3],
                            sK + SWZ128(row * 128 + colb));
            }
            #pragma unroll
            for (int nt = 0; nt < 8; nt++) {
                mma_f16(S[nt][0], S[nt][1], S[nt][2], S[nt][3],
                        af[2*kp][0], af[2*kp][1], af[2*kp][2], af[2*kp][3],
                        bs[nt][0], bs[nt][1]);
                mma_f16(S[nt][0], S[nt][1], S[nt][2], S[nt][3],
                        af[2*kp+1][0], af[2*kp+1][1], af[2*kp+1][2], af[2*kp+1][3],
                        bs[nt][2], bs[nt][3]);
            }
        }

        // ---- P = relu(scale*S), causal mask; round fp16 + repack to A frags
        const bool diag = (kt == qt);
        uint32_t pha[4][4];
        #pragma unroll
        for (int ksp = 0; ksp < 4; ksp++) {
            #pragma unroll
            for (int u = 0; u < 2; u++) {
                const int ntile = 2 * ksp + u;
                float pv[4];
                #pragma unroll
                for (int c = 0; c < 4; c++) {
                    float v = fmaxf(S[ntile][c] * scale, 0.0f);
                    if (diag) {
                        const int col = ntile * 8 + cbase + (c & 1);
                        const int row = rlo + ((c >= 2) ? 8 : 0);
                        if (col > row) v = 0.0f;
                    }
                    pv[c] = v;
                }
                pha[ksp][2*u + 0] = pk_h2(__float2half_rn(pv[0]), __float2half_rn(pv[1]));
                pha[ksp][2*u + 1] = pk_h2(__float2half_rn(pv[2]), __float2half_rn(pv[3]));
            }
        }

        // ---- y += P16 · V16 (single pass); V frags via ldmatrix.trans
        #pragma unroll
        for (int kp = 0; kp < 2; kp++) {
            uint32_t bv[8][4];
            #pragma unroll
            for (int nt = 0; nt < 8; nt++) {
                const int row = kp * 32 + (lane >> 3) * 8 + (lane & 7);
                const int colb = nt * 16;
                ldmatrix_x4_trans(bv[nt][0], bv[nt][1], bv[nt][2], bv[nt][3],
                                  sV + SWZ128(row * 128 + colb));
            }
            #pragma unroll
            for (int nt = 0; nt < 8; nt++) {
                mma_f16(y[nt][0], y[nt][1], y[nt][2], y[nt][3],
                        pha[2*kp][0], pha[2*kp][1], pha[2*kp][2], pha[2*kp][3],
                        bv[nt][0], bv[nt][1]);
                mma_f16(y[nt][0], y[nt][1], y[nt][2], y[nt][3],
                        pha[2*kp+1][0], pha[2*kp+1][1], pha[2*kp+1][2], pha[2*kp+1][3],
                        bv[nt][2], bv[nt][3]);
            }
        }
        __syncthreads();
    }

    const int g = lane >> 2;
    #pragma unroll
    for (int nt = 0; nt < 8; nt++) {
        const int col = h * HS_ + nt * 8 + cbase;
        const int t0 = qt * 64 + warp * 16 + g;
        float2 v0; v0.x = y[nt][0]; v0.y = y[nt][1];
        float2 v1; v1.x = y[nt][2]; v1.y = y[nt][3];
        *reinterpret_cast<float2*>(out + ((size_t)b * T_ + t0) * C_ + col) = v0;
        *reinterpret_cast<float2*>(out + ((size_t)b * T_ + t0 + 8) * C_ + col) = v1;
    }
}

// ---------------------------------------------------------------------------
extern "C" void kernel_launch(void* const* d_in, const int* in_sizes, int n_in,
                              void* d_out, int out_size)
{
    const float* x    = (const float*)d_in[0];
    const float* W    = (const float*)d_in[1];
    const float* bias = (const float*)d_in[2];
    float* out = (float*)d_out;

    split_kernel<<<1184, 256>>>(x, W);

    cudaFuncSetAttribute(qkv_hmma_kernel,
                         cudaFuncAttributeMaxDynamicSharedMemorySize, GEMM_SMEM);
    qkv_hmma_kernel<<<dim3(N_TOT / 128, M_TOT / 128), 256, GEMM_SMEM>>>(bias);

    cudaFuncSetAttribute(attn_hmma_kernel,
                         cudaFuncAttributeMaxDynamicSharedMemorySize, AT_SMEM);
    attn_hmma_kernel<<<dim3(B_ * H_, T_ / 64), 128, AT_SMEM>>>(out);
}

// round 12
// speedup vs baseline: 1.0577x; 1.0577x over previous
#include <cuda_runtime.h>
#include <cuda_fp16.h>
#include <cstdint>

// Problem constants
#define B_  8
#define T_  1024
#define C_  768
#define H_  12
#define HS_ 64
#define M_TOT (B_*T_)        // 8192
#define N_TOT (3*C_)         // 2304
#define K_TOT C_             // 768

// ---------------------------------------------------------------------------
// Device-global scratch (fp16 single plane)
// ---------------------------------------------------------------------------
__device__ __align__(16) __half g_Q16[B_*H_*T_*HS_];
__device__ __align__(16) __half g_K16[B_*H_*T_*HS_];
__device__ __align__(16) __half g_V16[B_*H_*T_*HS_];

__device__ __align__(16) __half g_x16[M_TOT*K_TOT];
__device__ __align__(16) __half g_w16[N_TOT*K_TOT];

// ---------------------------------------------------------------------------
// PTX helpers (base ISA only)
// ---------------------------------------------------------------------------
__device__ __forceinline__ uint32_t smem_u32(const void* p) {
    uint32_t a;
    asm("{ .reg .u64 t; cvta.to.shared.u64 t, %1; cvt.u32.u64 %0, t; }"
        : "=r"(a) : "l"(p));
    return a;
}
__device__ __forceinline__ void cp_async16(uint32_t s, const void* g) {
    asm volatile("cp.async.cg.shared.global [%0], [%1], 16;" :: "r"(s), "l"(g));
}
__device__ __forceinline__ void cp_commit() {
    asm volatile("cp.async.commit_group;" ::: "memory");
}
__device__ __forceinline__ void cp_wait1() {
    asm volatile("cp.async.wait_group 1;" ::: "memory");
}
__device__ __forceinline__ void cp_wait0() {
    asm volatile("cp.async.wait_group 0;" ::: "memory");
}
__device__ __forceinline__ void ldmatrix_x4(uint32_t& r0, uint32_t& r1,
                                            uint32_t& r2, uint32_t& r3,
                                            uint32_t addr) {
    asm volatile("ldmatrix.sync.aligned.m8n8.x4.shared.b16 {%0,%1,%2,%3}, [%4];"
                 : "=r"(r0), "=r"(r1), "=r"(r2), "=r"(r3) : "r"(addr));
}
__device__ __forceinline__ void ldmatrix_x4_trans(uint32_t& r0, uint32_t& r1,
                                                  uint32_t& r2, uint32_t& r3,
                                                  uint32_t addr) {
    asm volatile("ldmatrix.sync.aligned.m8n8.x4.trans.shared.b16 {%0,%1,%2,%3}, [%4];"
                 : "=r"(r0), "=r"(r1), "=r"(r2), "=r"(r3) : "r"(addr));
}
__device__ __forceinline__ void mma_f16(float& c0, float& c1, float& c2, float& c3,
                                        uint32_t a0, uint32_t a1, uint32_t a2, uint32_t a3,
                                        uint32_t b0, uint32_t b1) {
    asm volatile(
        "mma.sync.aligned.m16n8k16.row.col.f32.f16.f16.f32 "
        "{%0,%1,%2,%3}, {%4,%5,%6,%7}, {%8,%9}, {%0,%1,%2,%3};"
        : "+f"(c0), "+f"(c1), "+f"(c2), "+f"(c3)
        : "r"(a0), "r"(a1), "r"(a2), "r"(a3), "r"(b0), "r"(b1));
}
__device__ __forceinline__ uint32_t pk_h2(__half lo, __half hi) {
    __half2 v = __halves2half2(lo, hi);
    return *reinterpret_cast<uint32_t*>(&v);
}
#define SWZ128(o) ((o) ^ (((o) >> 3) & 0x70))

// ---------------------------------------------------------------------------
// Kernel 0: fp32 -> fp16 single plane for x and W
// ---------------------------------------------------------------------------
__global__ __launch_bounds__(256) void split_kernel(const float* __restrict__ x,
                                                    const float* __restrict__ W)
{
    const int nqx = (M_TOT * K_TOT) / 4;
    const int nqw = (N_TOT * K_TOT) / 4;
    for (int q = blockIdx.x * blockDim.x + threadIdx.x; q < nqx + nqw;
         q += gridDim.x * blockDim.x) {
        const float4* src; __half* dst; int qq;
        if (q < nqx) { src = (const float4*)x; dst = g_x16; qq = q; }
        else         { src = (const float4*)W; dst = g_w16; qq = q - nqx; }
        const float4 v = src[qq];
        __half2* p = (__half2*)(dst + (size_t)qq * 4);
        p[0] = __halves2half2(__float2half_rn(v.x), __float2half_rn(v.y));
        p[1] = __halves2half2(__float2half_rn(v.z), __float2half_rn(v.w));
    }
}

// ---------------------------------------------------------------------------
// Kernel 1: HMMA QKV GEMM — fp16 single pass, 3-stage pipeline,
// ONE __syncthreads per iteration (fill placed after the barrier:
// fill(i+2) writes buffer (i-1)%3 whose readers all passed the sync).
// ---------------------------------------------------------------------------
#define ROWB 80
#define TILE_B (128*ROWB)
#define BUF_B  (2*TILE_B)        // 20480 B per stage
#define GEMM_SMEM (3*BUF_B)      // 61440 B
#define NITER  24

__global__ __launch_bounds__(256) void qkv_hmma_kernel(const float* __restrict__ bias)
{
    extern __shared__ char smg[];
    const uint32_t sbase = smem_u32(smg);

    const int tid  = threadIdx.x;
    const int warp = tid >> 5;
    const int lane = tid & 31;
    const int m0 = blockIdx.y * 128;
    const int n0 = blockIdx.x * 128;
    const int wm0 = (warp >> 2) * 64;
    const int wn0 = (warp & 3) * 32;

    auto fill = [&](int it, int buf) {
        const int kc = it * 32;
        const uint32_t base = sbase + buf * BUF_B;
        #pragma unroll
        for (int j = 0; j < 4; j++) {
            const int seg = tid + j * 256;
            const int arr = seg >> 9;
            const int w = seg & 511;
            const int r = w >> 2, c = w & 3;
            const __half* src = (arr == 0) ? g_x16 : g_w16;
            const int row = ((arr == 0) ? m0 : n0) + r;
            cp_async16(base + arr * TILE_B + r * ROWB + c * 16,
                       src + (size_t)row * K_TOT + kc + c * 8);
        }
        cp_commit();
    };

    float acc[4][4][4] = {};

    fill(0, 0);
    fill(1, 1);

    for (int i = 0; i < NITER; i++) {
        const int buf = i % 3;
        // wait for fill(i); at most fill(i+1) may remain in flight
        if (i + 1 < NITER) cp_wait1(); else cp_wait0();
        __syncthreads();                       // fill(i) visible; iter i-1 reads done
        if (i + 2 < NITER) fill(i + 2, (i + 2) % 3);   // writes (i-1)%3 — safe

        const uint32_t sA = sbase + buf * BUF_B;
        const uint32_t sB = sA + TILE_B;

        uint32_t bf[4][4];
        #pragma unroll
        for (int nt = 0; nt < 4; nt++) {
            const int off = (wn0 + nt * 8 + (lane & 7)) * ROWB + (lane >> 3) * 16;
            ldmatrix_x4(bf[nt][0], bf[nt][1], bf[nt][2], bf[nt][3], sB + off);
        }

        #pragma unroll
        for (int ks = 0; ks < 2; ks++) {
            #pragma unroll
            for (int mt = 0; mt < 4; mt++) {
                const int off = (wm0 + mt * 16 + (lane & 15)) * ROWB
                              + ks * 32 + (lane >> 4) * 16;
                uint32_t a0, a1, a2, a3;
                ldmatrix_x4(a0, a1, a2, a3, sA + off);
                #pragma unroll
                for (int nt = 0; nt < 4; nt++) {
                    float* c = acc[mt][nt];
                    mma_f16(c[0], c[1], c[2], c[3], a0, a1, a2, a3,
                            bf[nt][ks * 2 + 0], bf[nt][ks * 2 + 1]);
                }
            }
        }
        // no trailing sync: next iteration's barrier closes these reads
    }

    // Epilogue: bias add; Q/K/V -> fp16 single plane, scatter [B,H,T,hs]
    const int g  = lane >> 2;
    const int tq = lane & 3;
    #pragma unroll
    for (int nt = 0; nt < 4; nt++) {
        const int n = n0 + wn0 + nt * 8 + tq * 2;
        const float b0 = __ldg(bias + n);
        const float b1 = __ldg(bias + n + 1);
        const int three = n / C_;
        const int rem   = n - three * C_;
        const int head  = rem >> 6;
        const int d     = rem & 63;
        __half* dst = (three == 0) ? g_Q16 : (three == 1) ? g_K16 : g_V16;
        #pragma unroll
        for (int mt = 0; mt < 4; mt++) {
            #pragma unroll
            for (int half = 0; half < 2; half++) {
                const int m = m0 + wm0 + mt * 16 + g + half * 8;
                const int bb = m >> 10;
                const int t  = m & 1023;
                const float f0 = acc[mt][nt][half * 2 + 0] + b0;
                const float f1 = acc[mt][nt][half * 2 + 1] + b1;
                const size_t idx = ((size_t)(bb * H_ + head) * T_ + t) * HS_ + d;
                *reinterpret_cast<__half2*>(dst + idx) =
                    __halves2half2(__float2half_rn(f0), __float2half_rn(f1));
            }
        }
    }
}

// ---------------------------------------------------------------------------
// Kernel 2: fused causal ReLU attention — EXACT R9 shape (64-q CTAs, 4 warps).
// smem: Q16 (8KB) + 2 x (K16|V16) buffers (2 x 16KB) = 40KB.
// ---------------------------------------------------------------------------
#define AT_BUF0  8192
#define AT_BUF_B 16384
#define AT_SMEM  40960

__global__ __launch_bounds__(128) void attn_hmma_kernel(float* __restrict__ out)
{
    extern __shared__ char smema[];
    const uint32_t sb = smem_u32(smema);
    const int tid  = threadIdx.x;
    const int warp = tid >> 5;
    const int lane = tid & 31;
    const int bh = blockIdx.x;
    const int qt = (int)gridDim.y - 1 - (int)blockIdx.y;  // heavy tiles first
    const int b  = bh / H_;
    const int h  = bh - b * H_;
    const size_t hbase = (size_t)bh * T_ * HS_;

    // ---- load Q tile (single plane), swizzled 128B rows
    {
        #pragma unroll
        for (int j = 0; j < 4; j++) {
            const int w = tid + j * 128;            // 0..511
            const int r = w >> 3, c = w & 7;
            cp_async16(sb + SWZ128(r * 128 + c * 16),
                       g_Q16 + hbase + (size_t)(qt * 64 + r) * HS_ + c * 8);
        }
    }
    auto fillkv = [&](int kt, int buf) {
        #pragma unroll
        for (int j = 0; j < 8; j++) {
            const int seg = tid + j * 128;          // 0..1023
            const int arr = seg >> 9;               // 0:K16 1:V16
            const int w = seg & 511;
            const int r = w >> 3, c = w & 7;
            const __half* src = arr ? g_V16 : g_K16;
            cp_async16(sb + AT_BUF0 + buf * AT_BUF_B + arr * 8192
                           + SWZ128(r * 128 + c * 16),
                       src + hbase + (size_t)(kt * 64 + r) * HS_ + c * 8);
        }
        cp_commit();
    };

    fillkv(0, 0);   // Q loads ride in this group

    float y[8][4] = {};
    const float scale = 0.125f;
    const int rlo = warp * 16 + (lane >> 2);
    const int cbase = 2 * (lane & 3);

    for (int kt = 0; kt <= qt; kt++) {
        const int buf = kt & 1;
        if (kt < qt) { fillkv(kt + 1, buf ^ 1); cp_wait1(); }
        else         { cp_wait0(); }
        __syncthreads();

        const uint32_t sQ = sb;
        const uint32_t sK = sb + AT_BUF0 + buf * AT_BUF_B;
        const uint32_t sV = sK + 8192;

        // ---- S = Q16 · K16^T (single pass)
        float S[8][4] = {};
        uint32_t af[4][4];
        #pragma unroll
        for (int ks = 0; ks < 4; ks++) {
            const int row = warp * 16 + (lane & 15);
            const int colb = ks * 32 + (lane >> 4) * 16;
            ldmatrix_x4(af[ks][0], af[ks][1], af[ks][2], af[ks][3],
                        sQ + SWZ128(row * 128 + colb));
        }
        #pragma unroll
        for (int kp = 0; kp < 2; kp++) {
            uint32_t bs[8][4];
            #pragma unroll
            for (int nt = 0; nt < 8; nt++) {
                const int row = nt * 8 + (lane & 7);
                const int colb = kp * 64 + (lane >> 3) * 16;
                ldmatrix_x4(bs[nt][0], bs[nt][1], bs[nt][2], bs[nt][3],
                            sK + SWZ128(row * 128 + colb));
            }
            #pragma unroll
            for (int nt = 0; nt < 8; nt++) {
                mma_f16(S[nt][0], S[nt][1], S[nt][2], S[nt][3],
                        af[2*kp][0], af[2*kp][1], af[2*kp][2], af[2*kp][3],
                        bs[nt][0], bs[nt][1]);
                mma_f16(S[nt][0], S[nt][1], S[nt][2], S[nt][3],
                        af[2*kp+1][0], af[2*kp+1][1], af[2*kp+1][2], af[2*kp+1][3],
                        bs[nt][2], bs[nt][3]);
            }
        }

        // ---- P = relu(scale*S), causal mask; round fp16 + repack to A frags
        const bool diag = (kt == qt);
        uint32_t pha[4][4];
        #pragma unroll
        for (int ksp = 0; ksp < 4; ksp++) {
            #pragma unroll
            for (int u = 0; u < 2; u++) {
                const int ntile = 2 * ksp + u;
                float pv[4];
                #pragma unroll
                for (int c = 0; c < 4; c++) {
                    float v = fmaxf(S[ntile][c] * scale, 0.0f);
                    if (diag) {
                        const int col = ntile * 8 + cbase + (c & 1);
                        const int row = rlo + ((c >= 2) ? 8 : 0);
                        if (col > row) v = 0.0f;
                    }
                    pv[c] = v;
                }
                pha[ksp][2*u + 0] = pk_h2(__float2half_rn(pv[0]), __float2half_rn(pv[1]));
                pha[ksp][2*u + 1] = pk_h2(__float2half_rn(pv[2]), __float2half_rn(pv[3]));
            }
        }

        // ---- y += P16 · V16 (single pass); V frags via ldmatrix.trans
        #pragma unroll
        for (int kp = 0; kp < 2; kp++) {
            uint32_t bv[8][4];
            #pragma unroll
            for (int nt = 0; nt < 8; nt++) {
                const int row = kp * 32 + (lane >> 3) * 8 + (lane & 7);
                const int colb = nt * 16;
                ldmatrix_x4_trans(bv[nt][0], bv[nt][1], bv[nt][2], bv[nt][3],
                                  sV + SWZ128(row * 128 + colb));
            }
            #pragma unroll
            for (int nt = 0; nt < 8; nt++) {
                mma_f16(y[nt][0], y[nt][1], y[nt][2], y[nt][3],
                        pha[2*kp][0], pha[2*kp][1], pha[2*kp][2], pha[2*kp][3],
                        bv[nt][0], bv[nt][1]);
                mma_f16(y[nt][0], y[nt][1], y[nt][2], y[nt][3],
                        pha[2*kp+1][0], pha[2*kp+1][1], pha[2*kp+1][2], pha[2*kp+1][3],
                        bv[nt][2], bv[nt][3]);
            }
        }
        __syncthreads();
    }

    const int g = lane >> 2;
    #pragma unroll
    for (int nt = 0; nt < 8; nt++) {
        const int col = h * HS_ + nt * 8 + cbase;
        const int t0 = qt * 64 + warp * 16 + g;
        float2 v0; v0.x = y[nt][0]; v0.y = y[nt][1];
        float2 v1; v1.x = y[nt][2]; v1.y = y[nt][3];
        *reinterpret_cast<float2*>(out + ((size_t)b * T_ + t0) * C_ + col) = v0;
        *reinterpret_cast<float2*>(out + ((size_t)b * T_ + t0 + 8) * C_ + col) = v1;
    }
}

// ---------------------------------------------------------------------------
extern "C" void kernel_launch(void* const* d_in, const int* in_sizes, int n_in,
                              void* d_out, int out_size)
{
    const float* x    = (const float*)d_in[0];
    const float* W    = (const float*)d_in[1];
    const float* bias = (const float*)d_in[2];
    float* out = (float*)d_out;

    split_kernel<<<1184, 256>>>(x, W);

    cudaFuncSetAttribute(qkv_hmma_kernel,
                         cudaFuncAttributeMaxDynamicSharedMemorySize, GEMM_SMEM);
    qkv_hmma_kernel<<<dim3(N_TOT / 128, M_TOT / 128), 256, GEMM_SMEM>>>(bias);

    cudaFuncSetAttribute(attn_hmma_kernel,
                         cudaFuncAttributeMaxDynamicSharedMemorySize, AT_SMEM);
    attn_hmma_kernel<<<dim3(B_ * H_, T_ / 64), 128, AT_SMEM>>>(out);
}

// round 13
// speedup vs baseline: 1.2049x; 1.1392x over previous
#include <cuda_runtime.h>
#include <cuda_fp16.h>
#include <cstdint>

// Problem constants
#define B_  8
#define T_  1024
#define C_  768
#define H_  12
#define HS_ 64
#define M_TOT (B_*T_)        // 8192
#define N_TOT (3*C_)         // 2304
#define K_TOT C_             // 768

// ---------------------------------------------------------------------------
// Device-global scratch (fp16 single plane)
// ---------------------------------------------------------------------------
__device__ __align__(16) __half g_Q16[B_*H_*T_*HS_];
__device__ __align__(16) __half g_K16[B_*H_*T_*HS_];
__device__ __align__(16) __half g_V16[B_*H_*T_*HS_];

__device__ __align__(16) __half g_x16[M_TOT*K_TOT];
__device__ __align__(16) __half g_w16[N_TOT*K_TOT];

// ---------------------------------------------------------------------------
// PTX helpers (base ISA only)
// ---------------------------------------------------------------------------
__device__ __forceinline__ uint32_t smem_u32(const void* p) {
    uint32_t a;
    asm("{ .reg .u64 t; cvta.to.shared.u64 t, %1; cvt.u32.u64 %0, t; }"
        : "=r"(a) : "l"(p));
    return a;
}
__device__ __forceinline__ void cp_async16(uint32_t s, const void* g) {
    asm volatile("cp.async.cg.shared.global [%0], [%1], 16;" :: "r"(s), "l"(g));
}
__device__ __forceinline__ void cp_commit() {
    asm volatile("cp.async.commit_group;" ::: "memory");
}
__device__ __forceinline__ void cp_wait1() {
    asm volatile("cp.async.wait_group 1;" ::: "memory");
}
__device__ __forceinline__ void cp_wait0() {
    asm volatile("cp.async.wait_group 0;" ::: "memory");
}
__device__ __forceinline__ void ldmatrix_x4(uint32_t& r0, uint32_t& r1,
                                            uint32_t& r2, uint32_t& r3,
                                            uint32_t addr) {
    asm volatile("ldmatrix.sync.aligned.m8n8.x4.shared.b16 {%0,%1,%2,%3}, [%4];"
                 : "=r"(r0), "=r"(r1), "=r"(r2), "=r"(r3) : "r"(addr));
}
__device__ __forceinline__ void ldmatrix_x4_trans(uint32_t& r0, uint32_t& r1,
                                                  uint32_t& r2, uint32_t& r3,
                                                  uint32_t addr) {
    asm volatile("ldmatrix.sync.aligned.m8n8.x4.trans.shared.b16 {%0,%1,%2,%3}, [%4];"
                 : "=r"(r0), "=r"(r1), "=r"(r2), "=r"(r3) : "r"(addr));
}
__device__ __forceinline__ void mma_f16(float& c0, float& c1, float& c2, float& c3,
                                        uint32_t a0, uint32_t a1, uint32_t a2, uint32_t a3,
                                        uint32_t b0, uint32_t b1) {
    asm volatile(
        "mma.sync.aligned.m16n8k16.row.col.f32.f16.f16.f32 "
        "{%0,%1,%2,%3}, {%4,%5,%6,%7}, {%8,%9}, {%0,%1,%2,%3};"
        : "+f"(c0), "+f"(c1), "+f"(c2), "+f"(c3)
        : "r"(a0), "r"(a1), "r"(a2), "r"(a3), "r"(b0), "r"(b1));
}
__device__ __forceinline__ uint32_t pk_h2(__half lo, __half hi) {
    __half2 v = __halves2half2(lo, hi);
    return *reinterpret_cast<uint32_t*>(&v);
}
#define SWZ128(o) ((o) ^ (((o) >> 3) & 0x70))

// ---------------------------------------------------------------------------
// Kernel 0: fp32 -> fp16 single plane for x and W (unchanged from R9)
// ---------------------------------------------------------------------------
__global__ __launch_bounds__(256) void split_kernel(const float* __restrict__ x,
                                                    const float* __restrict__ W)
{
    const int nqx = (M_TOT * K_TOT) / 4;
    const int nqw = (N_TOT * K_TOT) / 4;
    for (int q = blockIdx.x * blockDim.x + threadIdx.x; q < nqx + nqw;
         q += gridDim.x * blockDim.x) {
        const float4* src; __half* dst; int qq;
        if (q < nqx) { src = (const float4*)x; dst = g_x16; qq = q; }
        else         { src = (const float4*)W; dst = g_w16; qq = q - nqx; }
        const float4 v = src[qq];
        __half2* p = (__half2*)(dst + (size_t)qq * 4);
        p[0] = __halves2half2(__float2half_rn(v.x), __float2half_rn(v.y));
        p[1] = __halves2half2(__float2half_rn(v.z), __float2half_rn(v.w));
    }
}

// ---------------------------------------------------------------------------
// Kernel 1: HMMA QKV GEMM — fp16 single pass, BK=64, 2-stage double buffer.
// Row stride 144 B (64 fp16 + 16 pad): (9r+c) mod 32 distinct over any 8
// consecutive rows -> conflict-free ldmatrix phases.
// ---------------------------------------------------------------------------
#define ROWB2 144
#define TILE2_B (128*ROWB2)       // 18432 B per operand tile
#define BUF2_B  (2*TILE2_B)       // A + B per stage = 36864 B
#define GEMM_SMEM (2*BUF2_B)      // 73728 B
#define NITER2  12                // k chunks of 64

__global__ __launch_bounds__(256, 2) void qkv_hmma_kernel(const float* __restrict__ bias)
{
    extern __shared__ char smg[];
    const uint32_t sbase = smem_u32(smg);

    const int tid  = threadIdx.x;
    const int warp = tid >> 5;
    const int lane = tid & 31;
    const int m0 = blockIdx.y * 128;
    const int n0 = blockIdx.x * 128;
    const int wm0 = (warp >> 2) * 64;
    const int wn0 = (warp & 3) * 32;

    auto fill = [&](int it, int buf) {
        const int kc = it * 64;
        const uint32_t base = sbase + buf * BUF2_B;
        #pragma unroll
        for (int j = 0; j < 8; j++) {
            const int seg = tid + j * 256;        // 0..2047
            const int arr = seg >> 10;            // 0:A 1:B
            const int w = seg & 1023;
            const int r = w >> 3, c = w & 7;      // row 0..127, 16B chunk 0..7
            const __half* src = (arr == 0) ? g_x16 : g_w16;
            const int row = ((arr == 0) ? m0 : n0) + r;
            cp_async16(base + arr * TILE2_B + r * ROWB2 + c * 16,
                       src + (size_t)row * K_TOT + kc + c * 8);
        }
        cp_commit();
    };

    float acc[4][4][4] = {};

    fill(0, 0);

    for (int i = 0; i < NITER2; i++) {
        const int buf = i & 1;
        if (i + 1 < NITER2) fill(i + 1, buf ^ 1);
        if (i + 1 < NITER2) cp_wait1(); else cp_wait0();
        __syncthreads();

        const uint32_t sA = sbase + buf * BUF2_B;
        const uint32_t sB = sA + TILE2_B;

        // B fragments: 4 n-tiles x 2 column halves (each x4 = k32)
        uint32_t bf[4][2][4];
        #pragma unroll
        for (int nt = 0; nt < 4; nt++) {
            const int rowoff = (wn0 + nt * 8 + (lane & 7)) * ROWB2;
            #pragma unroll
            for (int hf = 0; hf < 2; hf++) {
                ldmatrix_x4(bf[nt][hf][0], bf[nt][hf][1], bf[nt][hf][2], bf[nt][hf][3],
                            sB + rowoff + hf * 64 + (lane >> 3) * 16);
            }
        }

        #pragma unroll
        for (int ks = 0; ks < 4; ks++) {          // four k16 steps
            #pragma unroll
            for (int mt = 0; mt < 4; mt++) {
                const int off = (wm0 + mt * 16 + (lane & 15)) * ROWB2
                              + ks * 32 + (lane >> 4) * 16;
                uint32_t a0, a1, a2, a3;
                ldmatrix_x4(a0, a1, a2, a3, sA + off);
                #pragma unroll
                for (int nt = 0; nt < 4; nt++) {
                    float* c = acc[mt][nt];
                    mma_f16(c[0], c[1], c[2], c[3], a0, a1, a2, a3,
                            bf[nt][ks >> 1][(ks & 1) * 2 + 0],
                            bf[nt][ks >> 1][(ks & 1) * 2 + 1]);
                }
            }
        }
        __syncthreads();
    }

    // Epilogue: bias add; Q/K/V -> fp16 single plane, scatter [B,H,T,hs]
    const int g  = lane >> 2;
    const int tq = lane & 3;
    #pragma unroll
    for (int nt = 0; nt < 4; nt++) {
        const int n = n0 + wn0 + nt * 8 + tq * 2;
        const float b0 = __ldg(bias + n);
        const float b1 = __ldg(bias + n + 1);
        const int three = n / C_;
        const int rem   = n - three * C_;
        const int head  = rem >> 6;
        const int d     = rem & 63;
        __half* dst = (three == 0) ? g_Q16 : (three == 1) ? g_K16 : g_V16;
        #pragma unroll
        for (int mt = 0; mt < 4; mt++) {
            #pragma unroll
            for (int half = 0; half < 2; half++) {
                const int m = m0 + wm0 + mt * 16 + g + half * 8;
                const int bb = m >> 10;
                const int t  = m & 1023;
                const float f0 = acc[mt][nt][half * 2 + 0] + b0;
                const float f1 = acc[mt][nt][half * 2 + 1] + b1;
                const size_t idx = ((size_t)(bb * H_ + head) * T_ + t) * HS_ + d;
                *reinterpret_cast<__half2*>(dst + idx) =
                    __halves2half2(__float2half_rn(f0), __float2half_rn(f1));
            }
        }
    }
}

// ---------------------------------------------------------------------------
// Kernel 2: fused causal ReLU attention — EXACT R9 shape (64-q CTAs, 4 warps).
// smem: Q16 (8KB) + 2 x (K16|V16) buffers (2 x 16KB) = 40KB.
// ---------------------------------------------------------------------------
#define AT_BUF0  8192
#define AT_BUF_B 16384
#define AT_SMEM  40960

__global__ __launch_bounds__(128) void attn_hmma_kernel(float* __restrict__ out)
{
    extern __shared__ char smema[];
    const uint32_t sb = smem_u32(smema);
    const int tid  = threadIdx.x;
    const int warp = tid >> 5;
    const int lane = tid & 31;
    const int bh = blockIdx.x;
    const int qt = (int)gridDim.y - 1 - (int)blockIdx.y;  // heavy tiles first
    const int b  = bh / H_;
    const int h  = bh - b * H_;
    const size_t hbase = (size_t)bh * T_ * HS_;

    // ---- load Q tile (single plane), swizzled 128B rows
    {
        #pragma unroll
        for (int j = 0; j < 4; j++) {
            const int w = tid + j * 128;            // 0..511
            const int r = w >> 3, c = w & 7;
            cp_async16(sb + SWZ128(r * 128 + c * 16),
                       g_Q16 + hbase + (size_t)(qt * 64 + r) * HS_ + c * 8);
        }
    }
    auto fillkv = [&](int kt, int buf) {
        #pragma unroll
        for (int j = 0; j < 8; j++) {
            const int seg = tid + j * 128;          // 0..1023
            const int arr = seg >> 9;               // 0:K16 1:V16
            const int w = seg & 511;
            const int r = w >> 3, c = w & 7;
            const __half* src = arr ? g_V16 : g_K16;
            cp_async16(sb + AT_BUF0 + buf * AT_BUF_B + arr * 8192
                           + SWZ128(r * 128 + c * 16),
                       src + hbase + (size_t)(kt * 64 + r) * HS_ + c * 8);
        }
        cp_commit();
    };

    fillkv(0, 0);   // Q loads ride in this group

    float y[8][4] = {};
    const float scale = 0.125f;
    const int rlo = warp * 16 + (lane >> 2);
    const int cbase = 2 * (lane & 3);

    for (int kt = 0; kt <= qt; kt++) {
        const int buf = kt & 1;
        if (kt < qt) { fillkv(kt + 1, buf ^ 1); cp_wait1(); }
        else         { cp_wait0(); }
        __syncthreads();

        const uint32_t sQ = sb;
        const uint32_t sK = sb + AT_BUF0 + buf * AT_BUF_B;
        const uint32_t sV = sK + 8192;

        // ---- S = Q16 · K16^T (single pass)
        float S[8][4] = {};
        uint32_t af[4][4];
        #pragma unroll
        for (int ks = 0; ks < 4; ks++) {
            const int row = warp * 16 + (lane & 15);
            const int colb = ks * 32 + (lane >> 4) * 16;
            ldmatrix_x4(af[ks][0], af[ks][1], af[ks][2], af[ks][3],
                        sQ + SWZ128(row * 128 + colb));
        }
        #pragma unroll
        for (int kp = 0; kp < 2; kp++) {
            uint32_t bs[8][4];
            #pragma unroll
            for (int nt = 0; nt < 8; nt++) {
                const int row = nt * 8 + (lane & 7);
                const int colb = kp * 64 + (lane >> 3) * 16;
                ldmatrix_x4(bs[nt][0], bs[nt][1], bs[nt][2], bs[nt][3],
                            sK + SWZ128(row * 128 + colb));
            }
            #pragma unroll
            for (int nt = 0; nt < 8; nt++) {
                mma_f16(S[nt][0], S[nt][1], S[nt][2], S[nt][3],
                        af[2*kp][0], af[2*kp][1], af[2*kp][2], af[2*kp][3],
                        bs[nt][0], bs[nt][1]);
                mma_f16(S[nt][0], S[nt][1], S[nt][2], S[nt][3],
                        af[2*kp+1][0], af[2*kp+1][1], af[2*kp+1][2], af[2*kp+1][3],
                        bs[nt][2], bs[nt][3]);
            }
        }

        // ---- P = relu(scale*S), causal mask; round fp16 + repack to A frags
        const bool diag = (kt == qt);
        uint32_t pha[4][4];
        #pragma unroll
        for (int ksp = 0; ksp < 4; ksp++) {
            #pragma unroll
            for (int u = 0; u < 2; u++) {
                const int ntile = 2 * ksp + u;
                float pv[4];
                #pragma unroll
                for (int c = 0; c < 4; c++) {
                    float v = fmaxf(S[ntile][c] * scale, 0.0f);
                    if (diag) {
                        const int col = ntile * 8 + cbase + (c & 1);
                        const int row = rlo + ((c >= 2) ? 8 : 0);
                        if (col > row) v = 0.0f;
                    }
                    pv[c] = v;
                }
                pha[ksp][2*u + 0] = pk_h2(__float2half_rn(pv[0]), __float2half_rn(pv[1]));
                pha[ksp][2*u + 1] = pk_h2(__float2half_rn(pv[2]), __float2half_rn(pv[3]));
            }
        }

        // ---- y += P16 · V16 (single pass); V frags via ldmatrix.trans
        #pragma unroll
        for (int kp = 0; kp < 2; kp++) {
            uint32_t bv[8][4];
            #pragma unroll
            for (int nt = 0; nt < 8; nt++) {
                const int row = kp * 32 + (lane >> 3) * 8 + (lane & 7);
                const int colb = nt * 16;
                ldmatrix_x4_trans(bv[nt][0], bv[nt][1], bv[nt][2], bv[nt][3],
                                  sV + SWZ128(row * 128 + colb));
            }
            #pragma unroll
            for (int nt = 0; nt < 8; nt++) {
                mma_f16(y[nt][0], y[nt][1], y[nt][2], y[nt][3],
                        pha[2*kp][0], pha[2*kp][1], pha[2*kp][2], pha[2*kp][3],
                        bv[nt][0], bv[nt][1]);
                mma_f16(y[nt][0], y[nt][1], y[nt][2], y[nt][3],
                        pha[2*kp+1][0], pha[2*kp+1][1], pha[2*kp+1][2], pha[2*kp+1][3],
                        bv[nt][2], bv[nt][3]);
            }
        }
        __syncthreads();
    }

    const int g = lane >> 2;
    #pragma unroll
    for (int nt = 0; nt < 8; nt++) {
        const int col = h * HS_ + nt * 8 + cbase;
        const int t0 = qt * 64 + warp * 16 + g;
        float2 v0; v0.x = y[nt][0]; v0.y = y[nt][1];
        float2 v1; v1.x = y[nt][2]; v1.y = y[nt][3];
        *reinterpret_cast<float2*>(out + ((size_t)b * T_ + t0) * C_ + col) = v0;
        *reinterpret_cast<float2*>(out + ((size_t)b * T_ + t0 + 8) * C_ + col) = v1;
    }
}

// ---------------------------------------------------------------------------
extern "C" void kernel_launch(void* const* d_in, const int* in_sizes, int n_in,
                              void* d_out, int out_size)
{
    const float* x    = (const float*)d_in[0];
    const float* W    = (const float*)d_in[1];
    const float* bias = (const float*)d_in[2];
    float* out = (float*)d_out;

    split_kernel<<<1184, 256>>>(x, W);

    cudaFuncSetAttribute(qkv_hmma_kernel,
                         cudaFuncAttributeMaxDynamicSharedMemorySize, GEMM_SMEM);
    qkv_hmma_kernel<<<dim3(N_TOT / 128, M_TOT / 128), 256, GEMM_SMEM>>>(bias);

    cudaFuncSetAttribute(attn_hmma_kernel,
                         cudaFuncAttributeMaxDynamicSharedMemorySize, AT_SMEM);
    attn_hmma_kernel<<<dim3(B_ * H_, T_ / 64), 128, AT_SMEM>>>(out);
}

// round 14
// speedup vs baseline: 1.2206x; 1.0130x over previous
#include <cuda_runtime.h>
#include <cuda_fp16.h>
#include <cstdint>

// Problem constants
#define B_  8
#define T_  1024
#define C_  768
#define H_  12
#define HS_ 64
#define M_TOT (B_*T_)        // 8192
#define N_TOT (3*C_)         // 2304
#define K_TOT C_             // 768

// ---------------------------------------------------------------------------
// Device-global scratch (fp16 single plane)
// ---------------------------------------------------------------------------
__device__ __align__(16) __half g_Q16[B_*H_*T_*HS_];
__device__ __align__(16) __half g_K16[B_*H_*T_*HS_];
__device__ __align__(16) __half g_V16[B_*H_*T_*HS_];

__device__ __align__(16) __half g_x16[M_TOT*K_TOT];
__device__ __align__(16) __half g_w16[N_TOT*K_TOT];

// ---------------------------------------------------------------------------
// PTX helpers (base ISA only)
// ---------------------------------------------------------------------------
__device__ __forceinline__ uint32_t smem_u32(const void* p) {
    uint32_t a;
    asm("{ .reg .u64 t; cvta.to.shared.u64 t, %1; cvt.u32.u64 %0, t; }"
        : "=r"(a) : "l"(p));
    return a;
}
__device__ __forceinline__ void cp_async16(uint32_t s, const void* g) {
    asm volatile("cp.async.cg.shared.global [%0], [%1], 16;" :: "r"(s), "l"(g));
}
__device__ __forceinline__ void cp_commit() {
    asm volatile("cp.async.commit_group;" ::: "memory");
}
__device__ __forceinline__ void cp_wait1() {
    asm volatile("cp.async.wait_group 1;" ::: "memory");
}
__device__ __forceinline__ void cp_wait0() {
    asm volatile("cp.async.wait_group 0;" ::: "memory");
}
__device__ __forceinline__ void ldmatrix_x4(uint32_t& r0, uint32_t& r1,
                                            uint32_t& r2, uint32_t& r3,
                                            uint32_t addr) {
    asm volatile("ldmatrix.sync.aligned.m8n8.x4.shared.b16 {%0,%1,%2,%3}, [%4];"
                 : "=r"(r0), "=r"(r1), "=r"(r2), "=r"(r3) : "r"(addr));
}
__device__ __forceinline__ void ldmatrix_x4_trans(uint32_t& r0, uint32_t& r1,
                                                  uint32_t& r2, uint32_t& r3,
                                                  uint32_t addr) {
    asm volatile("ldmatrix.sync.aligned.m8n8.x4.trans.shared.b16 {%0,%1,%2,%3}, [%4];"
                 : "=r"(r0), "=r"(r1), "=r"(r2), "=r"(r3) : "r"(addr));
}
__device__ __forceinline__ void mma_f16(float& c0, float& c1, float& c2, float& c3,
                                        uint32_t a0, uint32_t a1, uint32_t a2, uint32_t a3,
                                        uint32_t b0, uint32_t b1) {
    asm volatile(
        "mma.sync.aligned.m16n8k16.row.col.f32.f16.f16.f32 "
        "{%0,%1,%2,%3}, {%4,%5,%6,%7}, {%8,%9}, {%0,%1,%2,%3};"
        : "+f"(c0), "+f"(c1), "+f"(c2), "+f"(c3)
        : "r"(a0), "r"(a1), "r"(a2), "r"(a3), "r"(b0), "r"(b1));
}
__device__ __forceinline__ uint32_t pk_h2(__half lo, __half hi) {
    __half2 v = __halves2half2(lo, hi);
    return *reinterpret_cast<uint32_t*>(&v);
}
#define SWZ128(o) ((o) ^ (((o) >> 3) & 0x70))

// ---------------------------------------------------------------------------
// Kernel 0: fp32 -> fp16, MLP=2 (two independent float4 chains per thread).
// Grid covers all quads in one pass: x quads + w quads.
// ---------------------------------------------------------------------------
#define NQX ((M_TOT * K_TOT) / 4)      // 1572864
#define NQW ((N_TOT * K_TOT) / 4)      // 442368
#define NQTOT (NQX + NQW)              // 2015232

__global__ __launch_bounds__(256) void split_kernel(const float* __restrict__ x,
                                                    const float* __restrict__ W)
{
    const int base = (blockIdx.x * blockDim.x + threadIdx.x) * 2;
    // two independent quads
    #pragma unroll
    for (int u = 0; u < 2; u++) {
        const int q = base + u;
        if (q >= NQTOT) return;
        const float4* src; __half* dst; int qq;
        if (q < NQX) { src = (const float4*)x; dst = g_x16; qq = q; }
        else         { src = (const float4*)W; dst = g_w16; qq = q - NQX; }
        const float4 v = __ldg(src + qq);
        __half2* p = (__half2*)(dst + (size_t)qq * 4);
        p[0] = __halves2half2(__float2half_rn(v.x), __float2half_rn(v.y));
        p[1] = __halves2half2(__float2half_rn(v.z), __float2half_rn(v.w));
    }
}

// ---------------------------------------------------------------------------
// Kernel 1: HMMA QKV GEMM — fp16 single pass, BK=64, 2-stage (R13, unchanged).
// ---------------------------------------------------------------------------
#define ROWB2 144
#define TILE2_B (128*ROWB2)       // 18432 B per operand tile
#define BUF2_B  (2*TILE2_B)       // A + B per stage = 36864 B
#define GEMM_SMEM (2*BUF2_B)      // 73728 B
#define NITER2  12                // k chunks of 64

__global__ __launch_bounds__(256, 2) void qkv_hmma_kernel(const float* __restrict__ bias)
{
    extern __shared__ char smg[];
    const uint32_t sbase = smem_u32(smg);

    const int tid  = threadIdx.x;
    const int warp = tid >> 5;
    const int lane = tid & 31;
    const int m0 = blockIdx.y * 128;
    const int n0 = blockIdx.x * 128;
    const int wm0 = (warp >> 2) * 64;
    const int wn0 = (warp & 3) * 32;

    auto fill = [&](int it, int buf) {
        const int kc = it * 64;
        const uint32_t base = sbase + buf * BUF2_B;
        #pragma unroll
        for (int j = 0; j < 8; j++) {
            const int seg = tid + j * 256;        // 0..2047
            const int arr = seg >> 10;            // 0:A 1:B
            const int w = seg & 1023;
            const int r = w >> 3, c = w & 7;      // row 0..127, 16B chunk 0..7
            const __half* src = (arr == 0) ? g_x16 : g_w16;
            const int row = ((arr == 0) ? m0 : n0) + r;
            cp_async16(base + arr * TILE2_B + r * ROWB2 + c * 16,
                       src + (size_t)row * K_TOT + kc + c * 8);
        }
        cp_commit();
    };

    float acc[4][4][4] = {};

    fill(0, 0);

    for (int i = 0; i < NITER2; i++) {
        const int buf = i & 1;
        if (i + 1 < NITER2) fill(i + 1, buf ^ 1);
        if (i + 1 < NITER2) cp_wait1(); else cp_wait0();
        __syncthreads();

        const uint32_t sA = sbase + buf * BUF2_B;
        const uint32_t sB = sA + TILE2_B;

        uint32_t bf[4][2][4];
        #pragma unroll
        for (int nt = 0; nt < 4; nt++) {
            const int rowoff = (wn0 + nt * 8 + (lane & 7)) * ROWB2;
            #pragma unroll
            for (int hf = 0; hf < 2; hf++) {
                ldmatrix_x4(bf[nt][hf][0], bf[nt][hf][1], bf[nt][hf][2], bf[nt][hf][3],
                            sB + rowoff + hf * 64 + (lane >> 3) * 16);
            }
        }

        #pragma unroll
        for (int ks = 0; ks < 4; ks++) {
            #pragma unroll
            for (int mt = 0; mt < 4; mt++) {
                const int off = (wm0 + mt * 16 + (lane & 15)) * ROWB2
                              + ks * 32 + (lane >> 4) * 16;
                uint32_t a0, a1, a2, a3;
                ldmatrix_x4(a0, a1, a2, a3, sA + off);
                #pragma unroll
                for (int nt = 0; nt < 4; nt++) {
                    float* c = acc[mt][nt];
                    mma_f16(c[0], c[1], c[2], c[3], a0, a1, a2, a3,
                            bf[nt][ks >> 1][(ks & 1) * 2 + 0],
                            bf[nt][ks >> 1][(ks & 1) * 2 + 1]);
                }
            }
        }
        __syncthreads();
    }

    // Epilogue: bias add; Q/K/V -> fp16 single plane, scatter [B,H,T,hs]
    const int g  = lane >> 2;
    const int tq = lane & 3;
    #pragma unroll
    for (int nt = 0; nt < 4; nt++) {
        const int n = n0 + wn0 + nt * 8 + tq * 2;
        const float b0 = __ldg(bias + n);
        const float b1 = __ldg(bias + n + 1);
        const int three = n / C_;
        const int rem   = n - three * C_;
        const int head  = rem >> 6;
        const int d     = rem & 63;
        __half* dst = (three == 0) ? g_Q16 : (three == 1) ? g_K16 : g_V16;
        #pragma unroll
        for (int mt = 0; mt < 4; mt++) {
            #pragma unroll
            for (int half = 0; half < 2; half++) {
                const int m = m0 + wm0 + mt * 16 + g + half * 8;
                const int bb = m >> 10;
                const int t  = m & 1023;
                const float f0 = acc[mt][nt][half * 2 + 0] + b0;
                const float f1 = acc[mt][nt][half * 2 + 1] + b1;
                const size_t idx = ((size_t)(bb * H_ + head) * T_ + t) * HS_ + d;
                *reinterpret_cast<__half2*>(dst + idx) =
                    __halves2half2(__float2half_rn(f0), __float2half_rn(f1));
            }
        }
    }
}

// ---------------------------------------------------------------------------
// Kernel 2: fused causal ReLU attention — EXACT R9/R13 shape (unchanged).
// ---------------------------------------------------------------------------
#define AT_BUF0  8192
#define AT_BUF_B 16384
#define AT_SMEM  40960

__global__ __launch_bounds__(128) void attn_hmma_kernel(float* __restrict__ out)
{
    extern __shared__ char smema[];
    const uint32_t sb = smem_u32(smema);
    const int tid  = threadIdx.x;
    const int warp = tid >> 5;
    const int lane = tid & 31;
    const int bh = blockIdx.x;
    const int qt = (int)gridDim.y - 1 - (int)blockIdx.y;  // heavy tiles first
    const int b  = bh / H_;
    const int h  = bh - b * H_;
    const size_t hbase = (size_t)bh * T_ * HS_;

    {
        #pragma unroll
        for (int j = 0; j < 4; j++) {
            const int w = tid + j * 128;            // 0..511
            const int r = w >> 3, c = w & 7;
            cp_async16(sb + SWZ128(r * 128 + c * 16),
                       g_Q16 + hbase + (size_t)(qt * 64 + r) * HS_ + c * 8);
        }
    }
    auto fillkv = [&](int kt, int buf) {
        #pragma unroll
        for (int j = 0; j < 8; j++) {
            const int seg = tid + j * 128;          // 0..1023
            const int arr = seg >> 9;               // 0:K16 1:V16
            const int w = seg & 511;
            const int r = w >> 3, c = w & 7;
            const __half* src = arr ? g_V16 : g_K16;
            cp_async16(sb + AT_BUF0 + buf * AT_BUF_B + arr * 8192
                           + SWZ128(r * 128 + c * 16),
                       src + hbase + (size_t)(kt * 64 + r) * HS_ + c * 8);
        }
        cp_commit();
    };

    fillkv(0, 0);   // Q loads ride in this group

    float y[8][4] = {};
    const float scale = 0.125f;
    const int rlo = warp * 16 + (lane >> 2);
    const int cbase = 2 * (lane & 3);

    for (int kt = 0; kt <= qt; kt++) {
        const int buf = kt & 1;
        if (kt < qt) { fillkv(kt + 1, buf ^ 1); cp_wait1(); }
        else         { cp_wait0(); }
        __syncthreads();

        const uint32_t sQ = sb;
        const uint32_t sK = sb + AT_BUF0 + buf * AT_BUF_B;
        const uint32_t sV = sK + 8192;

        // ---- S = Q16 · K16^T (single pass)
        float S[8][4] = {};
        uint32_t af[4][4];
        #pragma unroll
        for (int ks = 0; ks < 4; ks++) {
            const int row = warp * 16 + (lane & 15);
            const int colb = ks * 32 + (lane >> 4) * 16;
            ldmatrix_x4(af[ks][0], af[ks][1], af[ks][2], af[ks][3],
                        sQ + SWZ128(row * 128 + colb));
        }
        #pragma unroll
        for (int kp = 0; kp < 2; kp++) {
            uint32_t bs[8][4];
            #pragma unroll
            for (int nt = 0; nt < 8; nt++) {
                const int row = nt * 8 + (lane & 7);
                const int colb = kp * 64 + (lane >> 3) * 16;
                ldmatrix_x4(bs[nt][0], bs[nt][1], bs[nt][2], bs[nt][3],
                            sK + SWZ128(row * 128 + colb));
            }
            #pragma unroll
            for (int nt = 0; nt < 8; nt++) {
                mma_f16(S[nt][0], S[nt][1], S[nt][2], S[nt][3],
                        af[2*kp][0], af[2*kp][1], af[2*kp][2], af[2*kp][3],
                        bs[nt][0], bs[nt][1]);
                mma_f16(S[nt][0], S[nt][1], S[nt][2], S[nt][3],
                        af[2*kp+1][0], af[2*kp+1][1], af[2*kp+1][2], af[2*kp+1][3],
                        bs[nt][2], bs[nt][3]);
            }
        }

        // ---- P = relu(scale*S), causal mask; round fp16 + repack to A frags
        const bool diag = (kt == qt);
        uint32_t pha[4][4];
        #pragma unroll
        for (int ksp = 0; ksp < 4; ksp++) {
            #pragma unroll
            for (int u = 0; u < 2; u++) {
                const int ntile = 2 * ksp + u;
                float pv[4];
                #pragma unroll
                for (int c = 0; c < 4; c++) {
                    float v = fmaxf(S[ntile][c] * scale, 0.0f);
                    if (diag) {
                        const int col = ntile * 8 + cbase + (c & 1);
                        const int row = rlo + ((c >= 2) ? 8 : 0);
                        if (col > row) v = 0.0f;
                    }
                    pv[c] = v;
                }
                pha[ksp][2*u + 0] = pk_h2(__float2half_rn(pv[0]), __float2half_rn(pv[1]));
                pha[ksp][2*u + 1] = pk_h2(__float2half_rn(pv[2]), __float2half_rn(pv[3]));
            }
        }

        // ---- y += P16 · V16 (single pass); V frags via ldmatrix.trans
        #pragma unroll
        for (int kp = 0; kp < 2; kp++) {
            uint32_t bv[8][4];
            #pragma unroll
            for (int nt = 0; nt < 8; nt++) {
                const int row = kp * 32 + (lane >> 3) * 8 + (lane & 7);
                const int colb = nt * 16;
                ldmatrix_x4_trans(bv[nt][0], bv[nt][1], bv[nt][2], bv[nt][3],
                                  sV + SWZ128(row * 128 + colb));
            }
            #pragma unroll
            for (int nt = 0; nt < 8; nt++) {
                mma_f16(y[nt][0], y[nt][1], y[nt][2], y[nt][3],
                        pha[2*kp][0], pha[2*kp][1], pha[2*kp][2], pha[2*kp][3],
                        bv[nt][0], bv[nt][1]);
                mma_f16(y[nt][0], y[nt][1], y[nt][2], y[nt][3],
                        pha[2*kp+1][0], pha[2*kp+1][1], pha[2*kp+1][2], pha[2*kp+1][3],
                        bv[nt][2], bv[nt][3]);
            }
        }
        __syncthreads();
    }

    const int g = lane >> 2;
    #pragma unroll
    for (int nt = 0; nt < 8; nt++) {
        const int col = h * HS_ + nt * 8 + cbase;
        const int t0 = qt * 64 + warp * 16 + g;
        float2 v0; v0.x = y[nt][0]; v0.y = y[nt][1];
        float2 v1; v1.x = y[nt][2]; v1.y = y[nt][3];
        *reinterpret_cast<float2*>(out + ((size_t)b * T_ + t0) * C_ + col) = v0;
        *reinterpret_cast<float2*>(out + ((size_t)b * T_ + t0 + 8) * C_ + col) = v1;
    }
}

// ---------------------------------------------------------------------------
extern "C" void kernel_launch(void* const* d_in, const int* in_sizes, int n_in,
                              void* d_out, int out_size)
{
    const float* x    = (const float*)d_in[0];
    const float* W    = (const float*)d_in[1];
    const float* bias = (const float*)d_in[2];
    float* out = (float*)d_out;

    // split: 2 quads per thread
    const int nthreads = (NQTOT + 1) / 2;
    split_kernel<<<(nthreads + 255) / 256, 256>>>(x, W);

    cudaFuncSetAttribute(qkv_hmma_kernel,
                         cudaFuncAttributeMaxDynamicSharedMemorySize, GEMM_SMEM);
    qkv_hmma_kernel<<<dim3(N_TOT / 128, M_TOT / 128), 256, GEMM_SMEM>>>(bias);

    cudaFuncSetAttribute(attn_hmma_kernel,
                         cudaFuncAttributeMaxDynamicSharedMemorySize, AT_SMEM);
    attn_hmma_kernel<<<dim3(B_ * H_, T_ / 64), 128, AT_SMEM>>>(out);
}